// round 15
// baseline (speedup 1.0000x reference)
#include <cuda_runtime.h>
#include <cuda_fp16.h>

// RK4 over tiny MLP (3 -> 8 -> 1, ReLU), fp32 I/O, fp16x2 core.
// R14 = R13 resubmitted verbatim (R13 bench died on a container infra error;
// no kernel signal). Changes vs R12 (26.8us best):
//  - u-trick: u_j = v_j * (p_j > 0). Bit-exact (mask is 1.0/0.0), and both
//    the k1 dot (sum u*p) and beta dot (sum u*w0) share u -> vw array gone
//    (-8 regs).
//  - C-setup weights (w1,w2,b1) stored UNIT-PAIR packed (12 regs vs 24
//    broadcasts); per-pair transpose to rows-in-lanes via __lows2half2/
//    __highs2half2 (+8 PRMT/pair on the idle alu pipe).
//  Weight footprint 49 -> 29 regs => __launch_bounds__(256,4): 24 -> 32
//  warps/SM. Kernel is latency-bound (issue 54%, fma 56%, DRAM 61%, nothing
//  saturated) so warps are the win.

#define DT       0.25f
#define HALF_DT  0.125f
#define DT6      (0.25f / 6.0f)

struct HW {
    __half2 w0[8];    // broadcast y0 coefficients (p fma + beta dot)
    __half2 v[8];     // broadcast W2 (u = v*mask)
    __half2 w1p[4];   // unit-pair packed y1 coefficients
    __half2 w2p[4];   // unit-pair packed y2 coefficients
    __half2 b1p[4];   // unit-pair packed b1
    __half2 b2p;
};

// One row pair (rows in half2 lanes) of frozen-activation RK4.
__device__ __forceinline__ float2 rk4_pair_frozen(const HW& W,
                                                  float y0A, float y1A, float y2A,
                                                  float y0B, float y1B, float y2B)
{
    const __half2 zero2 = __float2half2_rn(0.0f);
    const __half2 hdt2  = __float2half2_rn(HALF_DT);
    const __half2 two2  = __float2half2_rn(2.0f);

    // ---- C-setup in unit-pair layout, one row at a time ----
    __half2 y1A2 = __float2half2_rn(y1A);
    __half2 y2A2 = __float2half2_rn(y2A);
    __half2 y1B2 = __float2half2_rn(y1B);
    __half2 y2B2 = __float2half2_rn(y2B);

    __half2 cA[4], cB[4];
#pragma unroll
    for (int k = 0; k < 4; k++) {
        cA[k] = __hfma2(W.w1p[k], y1A2, __hfma2(W.w2p[k], y2A2, W.b1p[k]));
        cB[k] = __hfma2(W.w1p[k], y1B2, __hfma2(W.w2p[k], y2B2, W.b1p[k]));
    }

    // Transpose unit-pair -> rows-in-lanes: C_j = (c_j^A, c_j^B)
    __half2 C[8];
#pragma unroll
    for (int k = 0; k < 4; k++) {
        C[2 * k]     = __lows2half2(cA[k], cB[k]);
        C[2 * k + 1] = __highs2half2(cA[k], cB[k]);
    }

    // ---- Stage-1 pre-activations + shared masked dots ----
    __half2 y0p = __floats2half2_rn(y0A, y0B);

    __half2 a0 = W.b2p, a1 = zero2;      // k1 accumulators
    __half2 g0 = zero2,  g1 = zero2;     // beta accumulators
#pragma unroll
    for (int j = 0; j < 4; j++) {
        __half2 pj0 = __hfma2(W.w0[j],     y0p, C[j]);
        __half2 pj1 = __hfma2(W.w0[j + 4], y0p, C[j + 4]);
        __half2 u0  = __hmul2(W.v[j],     __hgt2(pj0, zero2));   // exact
        __half2 u1  = __hmul2(W.v[j + 4], __hgt2(pj1, zero2));
        a0 = __hfma2(u0, pj0, a0);
        a1 = __hfma2(u1, pj1, a1);
        g0 = __hfma2(u0, W.w0[j],     g0);
        g1 = __hfma2(u1, W.w0[j + 4], g1);
    }
    __half2 k1   = __hadd2(a0, a1);
    __half2 beta = __hadd2(g0, g1);

    // ---- Affine RK4 chain (active set frozen) ----
    __half2 bh = __hmul2(beta, hdt2);        // beta*dt/2
    __half2 bd = __hadd2(bh, bh);            // beta*dt
    __half2 k2 = __hfma2(bh, k1, k1);
    __half2 k3 = __hfma2(bh, k2, k1);
    __half2 k4 = __hfma2(bd, k3, k1);

    // K = k1 + 2(k2+k3) + k4 ; y = y0 + DT6*K (y0 exact fp32)
    __half2 t23 = __hadd2(k2, k3);
    __half2 t14 = __hadd2(k1, k4);
    __half2 Kp  = __hfma2(two2, t23, t14);

    float rA = fmaf(DT6, __low2float(Kp),  y0A);
    float rB = fmaf(DT6, __high2float(Kp), y0B);
    return make_float2(rA, rB);
}

template <bool GUARDED>
__global__ void __launch_bounds__(256, 4)
node_rk4_kernel(const float* __restrict__ x,
                const float* __restrict__ W1,
                const float* __restrict__ b1,
                const float* __restrict__ W2,
                const float* __restrict__ b2,
                float* __restrict__ out,
                int ngroups)   // ngroups = rows/4
{
    // ---- Load weights once per thread (lane-uniform -> L1 broadcast) ----
    const float4* W14 = reinterpret_cast<const float4*>(W1);
    float4 wA = __ldg(&W14[0]);
    float4 wB = __ldg(&W14[1]);
    float4 wC = __ldg(&W14[2]);
    float4 wD = __ldg(&W14[3]);
    float4 wE = __ldg(&W14[4]);
    float4 wF = __ldg(&W14[5]);
    const float4* b14 = reinterpret_cast<const float4*>(b1);
    float4 bA = __ldg(&b14[0]);
    float4 bB = __ldg(&b14[1]);
    const float4* W24 = reinterpret_cast<const float4*>(W2);
    float4 vA = __ldg(&W24[0]);
    float4 vB = __ldg(&W24[1]);
    float  b2s = __ldg(b2);

    HW W;
    // w0 broadcasts (y0 coefficients W1[3j])
    W.w0[0] = __float2half2_rn(wA.x);  W.w0[1] = __float2half2_rn(wA.w);
    W.w0[2] = __float2half2_rn(wB.z);  W.w0[3] = __float2half2_rn(wC.y);
    W.w0[4] = __float2half2_rn(wD.x);  W.w0[5] = __float2half2_rn(wD.w);
    W.w0[6] = __float2half2_rn(wE.z);  W.w0[7] = __float2half2_rn(wF.y);

    // v broadcasts (W2)
    W.v[0]  = __float2half2_rn(vA.x);  W.v[1]  = __float2half2_rn(vA.y);
    W.v[2]  = __float2half2_rn(vA.z);  W.v[3]  = __float2half2_rn(vA.w);
    W.v[4]  = __float2half2_rn(vB.x);  W.v[5]  = __float2half2_rn(vB.y);
    W.v[6]  = __float2half2_rn(vB.z);  W.v[7]  = __float2half2_rn(vB.w);

    // Unit-pair packed (lanes = units 2k, 2k+1)
    W.w1p[0] = __floats2half2_rn(wA.y, wB.x);
    W.w1p[1] = __floats2half2_rn(wB.w, wC.z);
    W.w1p[2] = __floats2half2_rn(wD.y, wE.x);
    W.w1p[3] = __floats2half2_rn(wE.w, wF.z);

    W.w2p[0] = __floats2half2_rn(wA.z, wB.y);
    W.w2p[1] = __floats2half2_rn(wC.x, wC.w);
    W.w2p[2] = __floats2half2_rn(wD.z, wE.y);
    W.w2p[3] = __floats2half2_rn(wF.x, wF.w);

    W.b1p[0] = __floats2half2_rn(bA.x, bA.y);
    W.b1p[1] = __floats2half2_rn(bA.z, bA.w);
    W.b1p[2] = __floats2half2_rn(bB.x, bB.y);
    W.b1p[3] = __floats2half2_rn(bB.z, bB.w);

    W.b2p = __float2half2_rn(b2s);

    const float4* x4   = reinterpret_cast<const float4*>(x);
    float4*       out4 = reinterpret_cast<float4*>(out);

    int g = blockIdx.x * blockDim.x + threadIdx.x;
    const int stride = gridDim.x * blockDim.x;

#pragma unroll
    for (int it = 0; it < 4; it++, g += stride) {
        if (!GUARDED || g < ngroups) {
            // 4 rows = 12 floats = 3 coalesced float4 loads
            float4 fa = __ldg(&x4[3 * g + 0]);
            float4 fb = __ldg(&x4[3 * g + 1]);
            float4 fc = __ldg(&x4[3 * g + 2]);

            float2 r01 = rk4_pair_frozen(W, fa.x, fa.y, fa.z,  fa.w, fb.x, fb.y);
            float2 r23 = rk4_pair_frozen(W, fb.z, fb.w, fc.x,  fc.y, fc.z, fc.w);

            out4[g] = make_float4(r01.x, r01.y, r23.x, r23.y);
        }
    }
}

extern "C" void kernel_launch(void* const* d_in, const int* in_sizes, int n_in,
                              void* d_out, int out_size)
{
    const float* x  = (const float*)d_in[0];
    const float* W1 = (const float*)d_in[1];
    const float* b1 = (const float*)d_in[2];
    const float* W2 = (const float*)d_in[3];
    const float* b2 = (const float*)d_in[4];
    float* out = (float*)d_out;

    int rows    = in_sizes[0] / 3;       // 8388608
    int ngroups = rows / 4;              // 2097152
    int block = 256;
    int total_threads = (ngroups + 3) / 4;   // 4 groups (16 rows) per thread
    int grid  = (total_threads + block - 1) / block;   // 2048

    bool exact = (rows % 4 == 0) &&
                 (ngroups % 4 == 0) &&
                 ((long long)grid * block * 4 == (long long)ngroups);

    if (exact)
        node_rk4_kernel<false><<<grid, block>>>(x, W1, b1, W2, b2, out, ngroups);
    else
        node_rk4_kernel<true ><<<grid, block>>>(x, W1, b1, W2, b2, out, ngroups);
}

// round 16
// speedup vs baseline: 1.1511x; 1.1511x over previous
#include <cuda_runtime.h>
#include <cuda_fp16.h>

// RK4 over tiny MLP (3 -> 8 -> 1, ReLU), fp32 I/O, fp16x2 core.
// R15 = R12 (best structure: broadcast weights in regs, frozen-activation RK4)
//   + persistent one-wave grid (numSMs*3 CTAs, grid-stride loop) — kills the
//     0.61-partial-wave tail of grid=2048 @ 3 CTAs/SM (~2us),
//   + closed-form RK4 combine: y = y0 + dt*k1*(1 + bh + 2/3 bh^2 + 1/3 bh^3),
//     bh = beta*dt/2 (Horner, 4 ops vs 7-op k2/k3/k4 chain),
//   + u-trick (u = v * (p>0), shared by k1-dot and beta-dot; bit-exact,
//     drops the vw array, regs 80 -> ~72).
// NO unit-pair weight packing (R14: transpose in critical path regressed).

#define DT       0.25f
#define HALF_DT  0.125f

struct HW {
    __half2 w0[8];   // broadcast y0 coefficients
    __half2 w1[8];   // y1 coefficients
    __half2 w2[8];   // y2 coefficients
    __half2 b1[8];
    __half2 v[8];    // W2
    __half2 b2p;
};

// One row pair (rows ride the half2 lanes) of frozen-activation RK4.
__device__ __forceinline__ float2 rk4_pair_frozen(const HW& W,
                                                  float y0A, float y1A, float y2A,
                                                  float y0B, float y1B, float y2B)
{
    const __half2 zero2 = __float2half2_rn(0.0f);
    const __half2 hdt2  = __float2half2_rn(HALF_DT);
    const __half2 one2  = __float2half2_rn(1.0f);
    const __half2 c23   = __float2half2_rn(2.0f / 3.0f);
    const __half2 c13   = __float2half2_rn(1.0f / 3.0f);

    __half2 y0p = __floats2half2_rn(y0A, y0B);
    __half2 y1p = __floats2half2_rn(y1A, y1B);
    __half2 y2p = __floats2half2_rn(y2A, y2B);

    // Stage-1 pre-activations + shared masked dots:
    //   u_j = v_j * (p_j > 0)        (exact: mask is 1.0/0.0)
    //   k1   = b2 + sum u_j p_j      (== b2 + sum v_j relu(p_j))
    //   beta = sum u_j w0_j
    __half2 a0 = W.b2p, a1 = zero2;
    __half2 g0 = zero2, g1 = zero2;
#pragma unroll
    for (int j = 0; j < 4; j++) {
        __half2 p0 = __hfma2(W.w0[j], y0p,
                     __hfma2(W.w1[j], y1p,
                     __hfma2(W.w2[j], y2p, W.b1[j])));
        __half2 p1 = __hfma2(W.w0[j + 4], y0p,
                     __hfma2(W.w1[j + 4], y1p,
                     __hfma2(W.w2[j + 4], y2p, W.b1[j + 4])));
        __half2 u0 = __hmul2(W.v[j],     __hgt2(p0, zero2));
        __half2 u1 = __hmul2(W.v[j + 4], __hgt2(p1, zero2));
        a0 = __hfma2(u0, p0, a0);
        a1 = __hfma2(u1, p1, a1);
        g0 = __hfma2(u0, W.w0[j],     g0);
        g1 = __hfma2(u1, W.w0[j + 4], g1);
    }
    __half2 k1   = __hadd2(a0, a1);
    __half2 beta = __hadd2(g0, g1);

    // Closed-form frozen RK4: y = y0 + dt*k1*(1 + bh + 2/3 bh^2 + 1/3 bh^3)
    __half2 bh = __hmul2(beta, hdt2);
    __half2 q  = __hfma2(c13, bh, c23);
    q          = __hfma2(q,  bh, one2);
    __half2 P  = __hfma2(q,  bh, one2);
    __half2 dk = __hmul2(k1, P);

    float rA = fmaf(DT, __low2float(dk),  y0A);
    float rB = fmaf(DT, __high2float(dk), y0B);
    return make_float2(rA, rB);
}

__global__ void __launch_bounds__(256, 3)
node_rk4_kernel(const float* __restrict__ x,
                const float* __restrict__ W1,
                const float* __restrict__ b1,
                const float* __restrict__ W2,
                const float* __restrict__ b2,
                float* __restrict__ out,
                int ngroups)   // ngroups = rows/4
{
    // ---- Load weights once per thread (lane-uniform -> L1 broadcast) ----
    const float4* W14 = reinterpret_cast<const float4*>(W1);
    float4 wA = __ldg(&W14[0]);
    float4 wB = __ldg(&W14[1]);
    float4 wC = __ldg(&W14[2]);
    float4 wD = __ldg(&W14[3]);
    float4 wE = __ldg(&W14[4]);
    float4 wF = __ldg(&W14[5]);
    const float4* b14 = reinterpret_cast<const float4*>(b1);
    float4 bA = __ldg(&b14[0]);
    float4 bB = __ldg(&b14[1]);
    const float4* W24 = reinterpret_cast<const float4*>(W2);
    float4 vA = __ldg(&W24[0]);
    float4 vB = __ldg(&W24[1]);
    float  b2s = __ldg(b2);

    HW W;
    W.w0[0] = __float2half2_rn(wA.x);  W.w0[1] = __float2half2_rn(wA.w);
    W.w0[2] = __float2half2_rn(wB.z);  W.w0[3] = __float2half2_rn(wC.y);
    W.w0[4] = __float2half2_rn(wD.x);  W.w0[5] = __float2half2_rn(wD.w);
    W.w0[6] = __float2half2_rn(wE.z);  W.w0[7] = __float2half2_rn(wF.y);

    W.w1[0] = __float2half2_rn(wA.y);  W.w1[1] = __float2half2_rn(wB.x);
    W.w1[2] = __float2half2_rn(wB.w);  W.w1[3] = __float2half2_rn(wC.z);
    W.w1[4] = __float2half2_rn(wD.y);  W.w1[5] = __float2half2_rn(wE.x);
    W.w1[6] = __float2half2_rn(wE.w);  W.w1[7] = __float2half2_rn(wF.z);

    W.w2[0] = __float2half2_rn(wA.z);  W.w2[1] = __float2half2_rn(wB.y);
    W.w2[2] = __float2half2_rn(wC.x);  W.w2[3] = __float2half2_rn(wC.w);
    W.w2[4] = __float2half2_rn(wD.z);  W.w2[5] = __float2half2_rn(wE.y);
    W.w2[6] = __float2half2_rn(wF.x);  W.w2[7] = __float2half2_rn(wF.w);

    W.b1[0] = __float2half2_rn(bA.x);  W.b1[1] = __float2half2_rn(bA.y);
    W.b1[2] = __float2half2_rn(bA.z);  W.b1[3] = __float2half2_rn(bA.w);
    W.b1[4] = __float2half2_rn(bB.x);  W.b1[5] = __float2half2_rn(bB.y);
    W.b1[6] = __float2half2_rn(bB.z);  W.b1[7] = __float2half2_rn(bB.w);

    W.v[0]  = __float2half2_rn(vA.x);  W.v[1]  = __float2half2_rn(vA.y);
    W.v[2]  = __float2half2_rn(vA.z);  W.v[3]  = __float2half2_rn(vA.w);
    W.v[4]  = __float2half2_rn(vB.x);  W.v[5]  = __float2half2_rn(vB.y);
    W.v[6]  = __float2half2_rn(vB.z);  W.v[7]  = __float2half2_rn(vB.w);

    W.b2p = __float2half2_rn(b2s);

    const float4* x4   = reinterpret_cast<const float4*>(x);
    float4*       out4 = reinterpret_cast<float4*>(out);

    // Persistent one-wave grid-stride loop (grid = numSMs * 3 CTAs).
    const int stride = gridDim.x * blockDim.x;
    for (int g = blockIdx.x * blockDim.x + threadIdx.x; g < ngroups; g += stride) {
        // 4 rows = 12 floats = 3 coalesced float4 loads
        float4 fa = __ldg(&x4[3 * g + 0]);
        float4 fb = __ldg(&x4[3 * g + 1]);
        float4 fc = __ldg(&x4[3 * g + 2]);

        float2 r01 = rk4_pair_frozen(W, fa.x, fa.y, fa.z,  fa.w, fb.x, fb.y);
        float2 r23 = rk4_pair_frozen(W, fb.z, fb.w, fc.x,  fc.y, fc.z, fc.w);

        out4[g] = make_float4(r01.x, r01.y, r23.x, r23.y);
    }
}

extern "C" void kernel_launch(void* const* d_in, const int* in_sizes, int n_in,
                              void* d_out, int out_size)
{
    const float* x  = (const float*)d_in[0];
    const float* W1 = (const float*)d_in[1];
    const float* b1 = (const float*)d_in[2];
    const float* W2 = (const float*)d_in[3];
    const float* b2 = (const float*)d_in[4];
    float* out = (float*)d_out;

    int rows    = in_sizes[0] / 3;       // 8388608
    int ngroups = rows / 4;              // 2097152

    // One exact wave: 3 CTAs/SM at <=85 regs, smem=0.
    int dev = 0, num_sms = 148;
    cudaGetDevice(&dev);
    cudaDeviceGetAttribute(&num_sms, cudaDevAttrMultiProcessorCount, dev);

    int block = 256;
    int grid  = num_sms * 3;
    if (grid > (ngroups + block - 1) / block)
        grid = (ngroups + block - 1) / block;

    node_rk4_kernel<<<grid, block>>>(x, W1, b1, W2, b2, out, ngroups);
}

// round 17
// speedup vs baseline: 1.1823x; 1.0271x over previous
#include <cuda_runtime.h>
#include <cuda_fp16.h>

// RK4 over tiny MLP (3 -> 8 -> 1, ReLU), fp32 I/O, fp16x2 core.
// R16 = R15 (frozen-activation + closed-form combine + persistent one-wave
// grid; 26.7us) + DOUBLE-BUFFERED PREFETCH:
//   R15 ncu shows the kernel is DRAM-latency bound (DRAM 56%, issue 47%,
//   fma 55%, everything else idle): each warp issues its 3 LDG.128 at loop
//   top and consumes them immediately -> full ~600cyc latency exposed per
//   iteration. Prefetching iteration i+1's loads before iteration i's
//   compute overlaps the round-trip with ~300cyc of math.
//   (R3's pipeline failed in the old COMPUTE-bound regime; conditions differ.)
// Plus __ldcs / __stcs streaming hints for x/out (no reuse).

#define DT       0.25f
#define HALF_DT  0.125f

struct HW {
    __half2 w0[8];   // broadcast y0 coefficients
    __half2 w1[8];   // y1 coefficients
    __half2 w2[8];   // y2 coefficients
    __half2 b1[8];
    __half2 v[8];    // W2
    __half2 b2p;
};

// One row pair (rows ride the half2 lanes) of frozen-activation RK4.
__device__ __forceinline__ float2 rk4_pair_frozen(const HW& W,
                                                  float y0A, float y1A, float y2A,
                                                  float y0B, float y1B, float y2B)
{
    const __half2 zero2 = __float2half2_rn(0.0f);
    const __half2 hdt2  = __float2half2_rn(HALF_DT);
    const __half2 one2  = __float2half2_rn(1.0f);
    const __half2 c23   = __float2half2_rn(2.0f / 3.0f);
    const __half2 c13   = __float2half2_rn(1.0f / 3.0f);

    __half2 y0p = __floats2half2_rn(y0A, y0B);
    __half2 y1p = __floats2half2_rn(y1A, y1B);
    __half2 y2p = __floats2half2_rn(y2A, y2B);

    // Stage-1 pre-activations + shared masked dots:
    //   u_j = v_j * (p_j > 0)   (exact: mask is 1.0/0.0)
    //   k1   = b2 + sum u_j p_j
    //   beta = sum u_j w0_j
    __half2 a0 = W.b2p, a1 = zero2;
    __half2 g0 = zero2, g1 = zero2;
#pragma unroll
    for (int j = 0; j < 4; j++) {
        __half2 p0 = __hfma2(W.w0[j], y0p,
                     __hfma2(W.w1[j], y1p,
                     __hfma2(W.w2[j], y2p, W.b1[j])));
        __half2 p1 = __hfma2(W.w0[j + 4], y0p,
                     __hfma2(W.w1[j + 4], y1p,
                     __hfma2(W.w2[j + 4], y2p, W.b1[j + 4])));
        __half2 u0 = __hmul2(W.v[j],     __hgt2(p0, zero2));
        __half2 u1 = __hmul2(W.v[j + 4], __hgt2(p1, zero2));
        a0 = __hfma2(u0, p0, a0);
        a1 = __hfma2(u1, p1, a1);
        g0 = __hfma2(u0, W.w0[j],     g0);
        g1 = __hfma2(u1, W.w0[j + 4], g1);
    }
    __half2 k1   = __hadd2(a0, a1);
    __half2 beta = __hadd2(g0, g1);

    // Closed-form frozen RK4: y = y0 + dt*k1*(1 + bh + 2/3 bh^2 + 1/3 bh^3)
    __half2 bh = __hmul2(beta, hdt2);
    __half2 q  = __hfma2(c13, bh, c23);
    q          = __hfma2(q,  bh, one2);
    __half2 P  = __hfma2(q,  bh, one2);
    __half2 dk = __hmul2(k1, P);

    float rA = fmaf(DT, __low2float(dk),  y0A);
    float rB = fmaf(DT, __high2float(dk), y0B);
    return make_float2(rA, rB);
}

__global__ void __launch_bounds__(256, 3)
node_rk4_kernel(const float* __restrict__ x,
                const float* __restrict__ W1,
                const float* __restrict__ b1,
                const float* __restrict__ W2,
                const float* __restrict__ b2,
                float* __restrict__ out,
                int ngroups)   // ngroups = rows/4
{
    // ---- Load weights once per thread (lane-uniform -> L1 broadcast) ----
    const float4* W14 = reinterpret_cast<const float4*>(W1);
    float4 wA = __ldg(&W14[0]);
    float4 wB = __ldg(&W14[1]);
    float4 wC = __ldg(&W14[2]);
    float4 wD = __ldg(&W14[3]);
    float4 wE = __ldg(&W14[4]);
    float4 wF = __ldg(&W14[5]);
    const float4* b14 = reinterpret_cast<const float4*>(b1);
    float4 bA = __ldg(&b14[0]);
    float4 bB = __ldg(&b14[1]);
    const float4* W24 = reinterpret_cast<const float4*>(W2);
    float4 vA = __ldg(&W24[0]);
    float4 vB = __ldg(&W24[1]);
    float  b2s = __ldg(b2);

    HW W;
    W.w0[0] = __float2half2_rn(wA.x);  W.w0[1] = __float2half2_rn(wA.w);
    W.w0[2] = __float2half2_rn(wB.z);  W.w0[3] = __float2half2_rn(wC.y);
    W.w0[4] = __float2half2_rn(wD.x);  W.w0[5] = __float2half2_rn(wD.w);
    W.w0[6] = __float2half2_rn(wE.z);  W.w0[7] = __float2half2_rn(wF.y);

    W.w1[0] = __float2half2_rn(wA.y);  W.w1[1] = __float2half2_rn(wB.x);
    W.w1[2] = __float2half2_rn(wB.w);  W.w1[3] = __float2half2_rn(wC.z);
    W.w1[4] = __float2half2_rn(wD.y);  W.w1[5] = __float2half2_rn(wE.x);
    W.w1[6] = __float2half2_rn(wE.w);  W.w1[7] = __float2half2_rn(wF.z);

    W.w2[0] = __float2half2_rn(wA.z);  W.w2[1] = __float2half2_rn(wB.y);
    W.w2[2] = __float2half2_rn(wC.x);  W.w2[3] = __float2half2_rn(wC.w);
    W.w2[4] = __float2half2_rn(wD.z);  W.w2[5] = __float2half2_rn(wE.y);
    W.w2[6] = __float2half2_rn(wF.x);  W.w2[7] = __float2half2_rn(wF.w);

    W.b1[0] = __float2half2_rn(bA.x);  W.b1[1] = __float2half2_rn(bA.y);
    W.b1[2] = __float2half2_rn(bA.z);  W.b1[3] = __float2half2_rn(bA.w);
    W.b1[4] = __float2half2_rn(bB.x);  W.b1[5] = __float2half2_rn(bB.y);
    W.b1[6] = __float2half2_rn(bB.z);  W.b1[7] = __float2half2_rn(bB.w);

    W.v[0]  = __float2half2_rn(vA.x);  W.v[1]  = __float2half2_rn(vA.y);
    W.v[2]  = __float2half2_rn(vA.z);  W.v[3]  = __float2half2_rn(vA.w);
    W.v[4]  = __float2half2_rn(vB.x);  W.v[5]  = __float2half2_rn(vB.y);
    W.v[6]  = __float2half2_rn(vB.z);  W.v[7]  = __float2half2_rn(vB.w);

    W.b2p = __float2half2_rn(b2s);

    const float4* x4   = reinterpret_cast<const float4*>(x);
    float4*       out4 = reinterpret_cast<float4*>(out);

    const int stride = gridDim.x * blockDim.x;
    int g = blockIdx.x * blockDim.x + threadIdx.x;
    if (g >= ngroups) return;

    // ---- Software pipeline: prime current group's loads (streaming) ----
    float4 fa = __ldcs(&x4[3 * g + 0]);
    float4 fb = __ldcs(&x4[3 * g + 1]);
    float4 fc = __ldcs(&x4[3 * g + 2]);

    while (true) {
        int gn = g + stride;
        bool more = (gn < ngroups);
        // Clamped prefetch index: always issue the loads (branch-free in the
        // steady state; final trip re-reads g harmlessly).
        int gp = more ? gn : g;
        float4 na = __ldcs(&x4[3 * gp + 0]);
        float4 nb = __ldcs(&x4[3 * gp + 1]);
        float4 nc = __ldcs(&x4[3 * gp + 2]);

        // ---- Compute current group while next group's loads fly ----
        float2 r01 = rk4_pair_frozen(W, fa.x, fa.y, fa.z,  fa.w, fb.x, fb.y);
        float2 r23 = rk4_pair_frozen(W, fb.z, fb.w, fc.x,  fc.y, fc.z, fc.w);
        __stcs(&out4[g], make_float4(r01.x, r01.y, r23.x, r23.y));

        if (!more) break;
        fa = na; fb = nb; fc = nc;
        g = gn;
    }
}

extern "C" void kernel_launch(void* const* d_in, const int* in_sizes, int n_in,
                              void* d_out, int out_size)
{
    const float* x  = (const float*)d_in[0];
    const float* W1 = (const float*)d_in[1];
    const float* b1 = (const float*)d_in[2];
    const float* W2 = (const float*)d_in[3];
    const float* b2 = (const float*)d_in[4];
    float* out = (float*)d_out;

    int rows    = in_sizes[0] / 3;       // 8388608
    int ngroups = rows / 4;              // 2097152

    // One exact wave: 3 CTAs/SM, smem=0.
    int dev = 0, num_sms = 148;
    cudaGetDevice(&dev);
    cudaDeviceGetAttribute(&num_sms, cudaDevAttrMultiProcessorCount, dev);

    int block = 256;
    int grid  = num_sms * 3;
    int max_grid = (ngroups + block - 1) / block;
    if (grid > max_grid) grid = max_grid;

    node_rk4_kernel<<<grid, block>>>(x, W1, b1, W2, b2, out, ngroups);
}